// round 10
// baseline (speedup 1.0000x reference)
#include <cuda_runtime.h>
#include <cuda_bf16.h>
#include <math.h>
#include <stdint.h>

// ---------------------------------------------------------------------------
// DistMultDecoder: out[e] = sigmoid( z[src_e] . (W + W^T) . z[dst_e] )
//   Wsym = W + W^T ; Y = Z @ Wsym ; out[e] = sigmoid(dot(Y[src], Z[dst]))
// GEMM: mma.sync bf16 2-term Dekker split (as R8/R9).
// Edge phase: edges bucketed by src>>6 (one-pass atomic scatter); one CTA per
// bucket -> src Y-rows L1-resident (~10x reuse). dst/slot loads via __ldcg
// (L1-bypass) so they don't evict src rows.
// ---------------------------------------------------------------------------

#define HID 128
#define MAX_NODES 100000
#define PAD_W 68
#define BSHIFT 6                 // 64 nodes per bucket
#define NBMAX 2048               // max buckets (nrows <= 131072)
#define CAP 1024                 // slots per bucket (mean ~640 for E=1M)

__device__ float g_Y[(size_t)MAX_NODES * HID];
__device__ int   g_is64;
__device__ __nv_bfloat16 g_Wh[HID * HID];
__device__ __nv_bfloat16 g_Wl[HID * HID];
__device__ int   g_cnt[NBMAX];
__device__ uint4 g_slot[(size_t)NBMAX * CAP];   // {src, dst, eid, pad}

// ---------------- kernel 0: zero bucket counters + detect idx dtype ---------
__global__ void prep_kernel(const int* __restrict__ ei32) {
    int idx = blockIdx.x * blockDim.x + threadIdx.x;
    if (idx < NBMAX) g_cnt[idx] = 0;
    if (idx == 0) {
        int s = 0;
        #pragma unroll
        for (int i = 1; i < 64; i += 2) s |= ei32[i];
        g_is64 = (s == 0) ? 1 : 0;   // int64 LE small values: odd words all 0
    }
}

// ---------------- kernel 1: Wsym = W + W^T -> bf16 hi/lo --------------------
__global__ void symm_kernel(const float* __restrict__ W) {
    int i = blockIdx.x * blockDim.x + threadIdx.x;   // 0..16383
    int n = i >> 7, k = i & 127;
    float v = W[n * HID + k] + W[k * HID + n];
    __nv_bfloat16 hi = __float2bfloat16(v);
    __nv_bfloat16 lo = __float2bfloat16(v - __bfloat162float(hi));
    g_Wh[i] = hi;
    g_Wl[i] = lo;
}

// ---------------- kernel 2: scatter edges into src-buckets ------------------
__global__ __launch_bounds__(256) void scatter_kernel(const void* __restrict__ ei, int E) {
    int is64 = g_is64;
    int stride = gridDim.x * blockDim.x;
    for (int e = blockIdx.x * blockDim.x + threadIdx.x; e < E; e += stride) {
        int src, dst;
        if (is64) {
            src = (int)((const long long*)ei)[e];
            dst = (int)((const long long*)ei)[(size_t)E + e];
        } else {
            src = ((const int*)ei)[e];
            dst = ((const int*)ei)[(size_t)E + e];
        }
        int b = src >> BSHIFT;
        int pos = atomicAdd(&g_cnt[b], 1);
        if (pos < CAP)
            g_slot[(size_t)b * CAP + pos] = make_uint4((unsigned)src, (unsigned)dst,
                                                       (unsigned)e, 0u);
    }
}

// ---------------- kernel 3: Y = Z @ Wsym via mma.sync bf16 (as R8) ----------
#define MMA16816(D, A0, A1, A2, A3, B0, B1)                                   \
    asm volatile("mma.sync.aligned.m16n8k16.row.col.f32.bf16.bf16.f32 "       \
                 "{%0,%1,%2,%3}, {%4,%5,%6,%7}, {%8,%9}, {%0,%1,%2,%3};"      \
                 : "+f"(D[0]), "+f"(D[1]), "+f"(D[2]), "+f"(D[3])             \
                 : "r"(A0), "r"(A1), "r"(A2), "r"(A3), "r"(B0), "r"(B1))

__device__ __forceinline__ uint32_t bf2_hi(float2 p) {
    __nv_bfloat162 h = __floats2bfloat162_rn(p.x, p.y);
    return *(uint32_t*)&h;
}
__device__ __forceinline__ uint32_t bf2_lo(float2 p, uint32_t hbits) {
    __nv_bfloat162 h = *(__nv_bfloat162*)&hbits;
    __nv_bfloat162 l = __floats2bfloat162_rn(p.x - __bfloat162float(h.x),
                                             p.y - __bfloat162float(h.y));
    return *(uint32_t*)&l;
}

__global__ __launch_bounds__(256, 2) void gemm_mma_kernel(const float* __restrict__ Z, int nrows) {
    extern __shared__ __align__(16) uint32_t sh[];
    uint32_t* WH = sh;
    uint32_t* WL = sh + 128 * PAD_W;

    int tid = threadIdx.x;
    {
        const uint32_t* gwh = (const uint32_t*)g_Wh;
        const uint32_t* gwl = (const uint32_t*)g_Wl;
        #pragma unroll
        for (int i = 0; i < 32; i++) {
            int idx  = tid + 256 * i;
            int row  = idx >> 6;
            int word = idx & 63;
            WH[row * PAD_W + word] = gwh[idx];
            WL[row * PAD_W + word] = gwl[idx];
        }
    }
    __syncthreads();

    int lane = tid & 31, w = tid >> 5;
    int g = lane >> 2, t = lane & 3;
    int r0 = (w & 3) * 32;
    int n0 = (w >> 2) * 64;

    int base = blockIdx.x * 128 + r0 + g;
    int rA[4] = { base, base + 8, base + 16, base + 24 };
    const float* zp[4];
    #pragma unroll
    for (int q = 0; q < 4; q++) {
        int r = rA[q] < nrows ? rA[q] : (nrows - 1);
        zp[q] = Z + (size_t)r * HID + 2 * t;
    }

    float d[2][8][4];
    #pragma unroll
    for (int m = 0; m < 2; m++)
        #pragma unroll
        for (int n = 0; n < 8; n++)
            #pragma unroll
            for (int q = 0; q < 4; q++) d[m][n][q] = 0.f;

    #pragma unroll
    for (int ks = 0; ks < 8; ks++) {
        int kb = ks * 16;
        float2 p00 = *(const float2*)(zp[0] + kb);
        float2 p01 = *(const float2*)(zp[0] + kb + 8);
        float2 p10 = *(const float2*)(zp[1] + kb);
        float2 p11 = *(const float2*)(zp[1] + kb + 8);
        float2 q00 = *(const float2*)(zp[2] + kb);
        float2 q01 = *(const float2*)(zp[2] + kb + 8);
        float2 q10 = *(const float2*)(zp[3] + kb);
        float2 q11 = *(const float2*)(zp[3] + kb + 8);

        uint32_t ah[2][4], al[2][4];
        ah[0][0] = bf2_hi(p00);  ah[0][1] = bf2_hi(p10);
        ah[0][2] = bf2_hi(p01);  ah[0][3] = bf2_hi(p11);
        ah[1][0] = bf2_hi(q00);  ah[1][1] = bf2_hi(q10);
        ah[1][2] = bf2_hi(q01);  ah[1][3] = bf2_hi(q11);
        al[0][0] = bf2_lo(p00, ah[0][0]);  al[0][1] = bf2_lo(p10, ah[0][1]);
        al[0][2] = bf2_lo(p01, ah[0][2]);  al[0][3] = bf2_lo(p11, ah[0][3]);
        al[1][0] = bf2_lo(q00, ah[1][0]);  al[1][1] = bf2_lo(q10, ah[1][1]);
        al[1][2] = bf2_lo(q01, ah[1][2]);  al[1][3] = bf2_lo(q11, ah[1][3]);

        int kw = ks * 8 + t;
        #pragma unroll
        for (int n = 0; n < 8; n++) {
            int nb = (n0 + 8 * n + g) * PAD_W + kw;
            uint32_t bh0 = WH[nb], bh1 = WH[nb + 4];
            uint32_t bl0 = WL[nb], bl1 = WL[nb + 4];
            #pragma unroll
            for (int m = 0; m < 2; m++) {
                MMA16816(d[m][n], ah[m][0], ah[m][1], ah[m][2], ah[m][3], bh0, bh1);
                MMA16816(d[m][n], ah[m][0], ah[m][1], ah[m][2], ah[m][3], bl0, bl1);
                MMA16816(d[m][n], al[m][0], al[m][1], al[m][2], al[m][3], bh0, bh1);
            }
        }
    }

    #pragma unroll
    for (int m = 0; m < 2; m++) {
        int r = base + 16 * m;
        #pragma unroll
        for (int n = 0; n < 8; n++) {
            int c = n0 + 8 * n + 2 * t;
            if (r < nrows)
                *(float2*)(g_Y + (size_t)r * HID + c) = make_float2(d[m][n][0], d[m][n][1]);
            if (r + 8 < nrows)
                *(float2*)(g_Y + (size_t)(r + 8) * HID + c) = make_float2(d[m][n][2], d[m][n][3]);
        }
    }
}

// ------------- kernel 4: bucketed edge gather + dot + sigmoid ---------------
// One CTA per bucket: src rows (<=64, 32KB) become L1-resident; dst & slot
// loads bypass L1 (__ldcg). 8 lanes/edge, 8 edges/warp (two 4-edge batches).
__global__ __launch_bounds__(256) void edge_bucket_kernel(const float* __restrict__ Z,
                                                          float* __restrict__ out) {
    const unsigned FULL = 0xFFFFFFFFu;
    int b = blockIdx.x;
    int cnt = g_cnt[b];
    if (cnt > CAP) cnt = CAP;
    const uint4* slots = g_slot + (size_t)b * CAP;

    int tid  = threadIdx.x;
    int w    = tid >> 5;
    int lane = tid & 31;
    int grp  = lane >> 3;        // 0..3
    int sub  = lane & 7;         // 0..7

    for (int jb = w * 8; jb < cnt; jb += 64) {
        // lanes 0..7: load slot for edge jb+lane
        unsigned sval = 0, dval = 0, eid = 0;
        bool mine = (lane < 8) && (jb + lane < cnt);
        if (mine) {
            uint4 sl = __ldcg(&slots[jb + lane]);
            sval = sl.x; dval = sl.y; eid = sl.z;
        }
        int s0 = __shfl_sync(FULL, (int)sval, grp);
        int s1 = __shfl_sync(FULL, (int)sval, 4 + grp);
        int d0 = __shfl_sync(FULL, (int)dval, grp);
        int d1 = __shfl_sync(FULL, (int)dval, 4 + grp);

        const float4* Ya0 = (const float4*)(g_Y + (size_t)s0 * HID);
        const float4* Zb0 = (const float4*)(Z   + (size_t)d0 * HID);
        const float4* Ya1 = (const float4*)(g_Y + (size_t)s1 * HID);
        const float4* Zb1 = (const float4*)(Z   + (size_t)d1 * HID);

        // src via L1 (reused ~10x within bucket); dst via L2-only
        float4 a0 = Ya0[sub];       float4 b0 = __ldcg(&Zb0[sub]);
        float4 a1 = Ya0[sub + 8];   float4 b1 = __ldcg(&Zb0[sub + 8]);
        float4 a2 = Ya0[sub + 16];  float4 b2 = __ldcg(&Zb0[sub + 16]);
        float4 a3 = Ya0[sub + 24];  float4 b3 = __ldcg(&Zb0[sub + 24]);
        float4 c0 = Ya1[sub];       float4 e0v = __ldcg(&Zb1[sub]);
        float4 c1 = Ya1[sub + 8];   float4 e1v = __ldcg(&Zb1[sub + 8]);
        float4 c2 = Ya1[sub + 16];  float4 e2v = __ldcg(&Zb1[sub + 16]);
        float4 c3 = Ya1[sub + 24];  float4 e3v = __ldcg(&Zb1[sub + 24]);

        float v0 = a0.x * b0.x + a0.y * b0.y + a0.z * b0.z + a0.w * b0.w;
        v0 += a1.x * b1.x + a1.y * b1.y + a1.z * b1.z + a1.w * b1.w;
        v0 += a2.x * b2.x + a2.y * b2.y + a2.z * b2.z + a2.w * b2.w;
        v0 += a3.x * b3.x + a3.y * b3.y + a3.z * b3.z + a3.w * b3.w;

        float v1 = c0.x * e0v.x + c0.y * e0v.y + c0.z * e0v.z + c0.w * e0v.w;
        v1 += c1.x * e1v.x + c1.y * e1v.y + c1.z * e1v.z + c1.w * e1v.w;
        v1 += c2.x * e2v.x + c2.y * e2v.y + c2.z * e2v.z + c2.w * e2v.w;
        v1 += c3.x * e3v.x + c3.y * e3v.y + c3.z * e3v.z + c3.w * e3v.w;

        v0 += __shfl_xor_sync(FULL, v0, 1);
        v1 += __shfl_xor_sync(FULL, v1, 1);
        v0 += __shfl_xor_sync(FULL, v0, 2);
        v1 += __shfl_xor_sync(FULL, v1, 2);
        v0 += __shfl_xor_sync(FULL, v0, 4);
        v1 += __shfl_xor_sync(FULL, v1, 4);

        float vg0 = __shfl_sync(FULL, v0, (lane & 3) << 3);
        float vg1 = __shfl_sync(FULL, v1, (lane & 3) << 3);
        float vg  = (lane < 4) ? vg0 : vg1;

        if (mine) out[eid] = 1.0f / (1.0f + expf(-vg));
    }
}

// ---------------------------------------------------------------------------
extern "C" void kernel_launch(void* const* d_in, const int* in_sizes, int n_in,
                              void* d_out, int out_size) {
    // Map inputs by element count: W = 16384; z = largest; edge_index = the rest.
    int wi = -1;
    for (int i = 0; i < n_in; i++) if (in_sizes[i] == HID * HID) { wi = i; break; }
    int zi = -1;
    for (int i = 0; i < n_in; i++) {
        if (i == wi) continue;
        if (zi < 0 || in_sizes[i] > in_sizes[zi]) zi = i;
    }
    int eii = -1;
    for (int i = 0; i < n_in; i++) if (i != wi && i != zi) { eii = i; break; }

    const float* W  = (const float*)d_in[wi];
    const float* z  = (const float*)d_in[zi];
    const void*  ei = d_in[eii];

    float* out = (float*)d_out;
    int nrows = in_sizes[zi] / HID;
    int E     = in_sizes[eii] / 2;

    prep_kernel<<<2, 1024>>>((const int*)ei);
    symm_kernel<<<64, 256>>>(W);
    scatter_kernel<<<512, 256>>>(ei, E);

    int smem = 2 * 128 * PAD_W * (int)sizeof(uint32_t);   // 69632 B
    cudaFuncSetAttribute(gemm_mma_kernel, cudaFuncAttributeMaxDynamicSharedMemorySize, smem);
    int gblocks = (nrows + 127) / 128;
    gemm_mma_kernel<<<gblocks, 256, smem>>>(z, nrows);

    int nb = (nrows + (1 << BSHIFT) - 1) >> BSHIFT;
    edge_bucket_kernel<<<nb, 256>>>(z, out);
}

// round 11
// speedup vs baseline: 1.9340x; 1.9340x over previous
#include <cuda_runtime.h>
#include <cuda_bf16.h>
#include <math.h>
#include <stdint.h>

// ---------------------------------------------------------------------------
// DistMultDecoder: out[e] = sigmoid( z[src_e] . (W + W^T) . z[dst_e] )
//   Wsym = W + W^T ; Y = Z @ Wsym ; out[e] = sigmoid(dot(Y[src], Z[dst]))
// GEMM: mma.sync bf16 2-term Dekker split  Y = Zh*Wh + Zh*Wl + Zl*Wh.
// Warp n-range processed in TWO halves (32 accums each) -> no register spills.
// Edge: flat, 8 lanes/edge, 8 edges/warp, 16 LDG.128 in flight (R8 version).
// ---------------------------------------------------------------------------

#define HID 128
#define MAX_NODES 100000
#define PAD_W 68   // words/row: frag LDS bank = (4g+t) mod 32, conflict-free

__device__ float g_Y[(size_t)MAX_NODES * HID];
__device__ int   g_is64;
__device__ __nv_bfloat16 g_Wh[HID * HID];   // Wsym hi, row-major [n][k]
__device__ __nv_bfloat16 g_Wl[HID * HID];   // Wsym lo

// ------- kernel 1: Wsym = W + W^T -> bf16 hi/lo ; + index-dtype detect ------
__global__ void symm_kernel(const float* __restrict__ W, const int* __restrict__ ei32) {
    if (blockIdx.x == 0 && threadIdx.x == 0) {
        int s = 0;
        #pragma unroll
        for (int i = 1; i < 64; i += 2) s |= ei32[i];
        g_is64 = (s == 0) ? 1 : 0;          // int64 LE small values: odd words all 0
    }
    int i = blockIdx.x * blockDim.x + threadIdx.x;   // 0..16383
    int n = i >> 7, k = i & 127;
    float v = W[n * HID + k] + W[k * HID + n];       // Wsym[n][k]
    __nv_bfloat16 hi = __float2bfloat16(v);
    __nv_bfloat16 lo = __float2bfloat16(v - __bfloat162float(hi));
    g_Wh[i] = hi;
    g_Wl[i] = lo;
}

// ---------------- kernel 2: Y = Z @ Wsym via mma.sync bf16 ------------------
#define MMA16816(D, A0, A1, A2, A3, B0, B1)                                   \
    asm volatile("mma.sync.aligned.m16n8k16.row.col.f32.bf16.bf16.f32 "       \
                 "{%0,%1,%2,%3}, {%4,%5,%6,%7}, {%8,%9}, {%0,%1,%2,%3};"      \
                 : "+f"(D[0]), "+f"(D[1]), "+f"(D[2]), "+f"(D[3])             \
                 : "r"(A0), "r"(A1), "r"(A2), "r"(A3), "r"(B0), "r"(B1))

__device__ __forceinline__ uint32_t bf2_hi(float2 p) {
    __nv_bfloat162 h = __floats2bfloat162_rn(p.x, p.y);
    return *(uint32_t*)&h;
}
__device__ __forceinline__ uint32_t bf2_lo(float2 p, uint32_t hbits) {
    __nv_bfloat162 h = *(__nv_bfloat162*)&hbits;
    __nv_bfloat162 l = __floats2bfloat162_rn(p.x - __bfloat162float(h.x),
                                             p.y - __bfloat162float(h.y));
    return *(uint32_t*)&l;
}

__global__ __launch_bounds__(256) void gemm_mma_kernel(const float* __restrict__ Z, int nrows) {
    extern __shared__ __align__(16) uint32_t sh[];
    uint32_t* WH = sh;                    // 128 x 68 words (bf16x2)
    uint32_t* WL = sh + 128 * PAD_W;

    int tid = threadIdx.x;

    // ---- stage W hi/lo into padded smem (8192 words each, coalesced) ----
    {
        const uint32_t* gwh = (const uint32_t*)g_Wh;
        const uint32_t* gwl = (const uint32_t*)g_Wl;
        #pragma unroll
        for (int i = 0; i < 32; i++) {
            int idx  = tid + 256 * i;        // 0..8191
            int row  = idx >> 6;
            int word = idx & 63;
            WH[row * PAD_W + word] = gwh[idx];
            WL[row * PAD_W + word] = gwl[idx];
        }
    }
    __syncthreads();

    int lane = tid & 31, w = tid >> 5;
    int g = lane >> 2, t = lane & 3;
    int r0 = (w & 3) * 32;        // warp row base within CTA tile
    int n0 = (w >> 2) * 64;       // warp col base

    // Per-thread A rows (clamped for OOB; garbage accumulators never stored)
    int base = blockIdx.x * 128 + r0 + g;
    int rA[4] = { base, base + 8, base + 16, base + 24 };
    const float* zp[4];
    #pragma unroll
    for (int q = 0; q < 4; q++) {
        int r = rA[q] < nrows ? rA[q] : (nrows - 1);
        zp[q] = Z + (size_t)r * HID + 2 * t;
    }

    // Two n-halves of 4 n-tiles each: 32 accumulators live at a time.
    #pragma unroll
    for (int nh = 0; nh < 2; nh++) {
        int nbase = n0 + nh * 32;

        float d[2][4][4];
        #pragma unroll
        for (int m = 0; m < 2; m++)
            #pragma unroll
            for (int n = 0; n < 4; n++)
                #pragma unroll
                for (int q = 0; q < 4; q++) d[m][n][q] = 0.f;

        #pragma unroll
        for (int ks = 0; ks < 8; ks++) {
            int kb = ks * 16;
            float2 p00 = *(const float2*)(zp[0] + kb);
            float2 p01 = *(const float2*)(zp[0] + kb + 8);
            float2 p10 = *(const float2*)(zp[1] + kb);
            float2 p11 = *(const float2*)(zp[1] + kb + 8);
            float2 q00 = *(const float2*)(zp[2] + kb);
            float2 q01 = *(const float2*)(zp[2] + kb + 8);
            float2 q10 = *(const float2*)(zp[3] + kb);
            float2 q11 = *(const float2*)(zp[3] + kb + 8);

            uint32_t ah[2][4], al[2][4];
            ah[0][0] = bf2_hi(p00);  ah[0][1] = bf2_hi(p10);
            ah[0][2] = bf2_hi(p01);  ah[0][3] = bf2_hi(p11);
            ah[1][0] = bf2_hi(q00);  ah[1][1] = bf2_hi(q10);
            ah[1][2] = bf2_hi(q01);  ah[1][3] = bf2_hi(q11);
            al[0][0] = bf2_lo(p00, ah[0][0]);  al[0][1] = bf2_lo(p10, ah[0][1]);
            al[0][2] = bf2_lo(p01, ah[0][2]);  al[0][3] = bf2_lo(p11, ah[0][3]);
            al[1][0] = bf2_lo(q00, ah[1][0]);  al[1][1] = bf2_lo(q10, ah[1][1]);
            al[1][2] = bf2_lo(q01, ah[1][2]);  al[1][3] = bf2_lo(q11, ah[1][3]);

            int kw = ks * 8 + t;
            #pragma unroll
            for (int n = 0; n < 4; n++) {
                int nb = (nbase + 8 * n + g) * PAD_W + kw;
                uint32_t bh0 = WH[nb], bh1 = WH[nb + 4];
                uint32_t bl0 = WL[nb], bl1 = WL[nb + 4];
                #pragma unroll
                for (int m = 0; m < 2; m++) {
                    MMA16816(d[m][n], ah[m][0], ah[m][1], ah[m][2], ah[m][3], bh0, bh1);
                    MMA16816(d[m][n], ah[m][0], ah[m][1], ah[m][2], ah[m][3], bl0, bl1);
                    MMA16816(d[m][n], al[m][0], al[m][1], al[m][2], al[m][3], bh0, bh1);
                }
            }
        }

        // ---- epilogue for this n-half ----
        #pragma unroll
        for (int m = 0; m < 2; m++) {
            int r = base + 16 * m;
            #pragma unroll
            for (int n = 0; n < 4; n++) {
                int c = nbase + 8 * n + 2 * t;
                if (r < nrows)
                    *(float2*)(g_Y + (size_t)r * HID + c) = make_float2(d[m][n][0], d[m][n][1]);
                if (r + 8 < nrows)
                    *(float2*)(g_Y + (size_t)(r + 8) * HID + c) = make_float2(d[m][n][2], d[m][n][3]);
            }
        }
    }
}

// ------------------- kernel 3: per-edge gather + dot + sigmoid --------------
// 8 lanes/edge, 8 edges/warp in two 4-edge batches; 16 LDG.128 in flight.
__global__ __launch_bounds__(256) void edge_kernel(const void* __restrict__ ei,
                                                   const float* __restrict__ Z,
                                                   float* __restrict__ out, int E) {
    const unsigned FULL = 0xFFFFFFFFu;
    int gtid  = blockIdx.x * blockDim.x + threadIdx.x;
    int warp  = gtid >> 5;
    int lane  = gtid & 31;
    int grp   = lane >> 3;       // 0..3
    int sub   = lane & 7;        // 0..7

    long long e0 = (long long)warp * 8;
    if (e0 >= E) return;

    long long myidx = 0;
    int is64 = g_is64;
    if (lane < 16) {
        long long e = e0 + (lane & 7);
        if (e >= E) e = 0;
        size_t off = (lane < 8) ? (size_t)e : (size_t)E + (size_t)e;
        if (is64) myidx = ((const long long*)ei)[off];
        else      myidx = ((const int*)ei)[off];
    }
    long long s0 = __shfl_sync(FULL, myidx, grp);
    long long s1 = __shfl_sync(FULL, myidx, 4 + grp);
    long long d0 = __shfl_sync(FULL, myidx, 8 + grp);
    long long d1 = __shfl_sync(FULL, myidx, 12 + grp);

    const float4* Ya0 = (const float4*)(g_Y + (size_t)s0 * HID);
    const float4* Zb0 = (const float4*)(Z   + (size_t)d0 * HID);
    const float4* Ya1 = (const float4*)(g_Y + (size_t)s1 * HID);
    const float4* Zb1 = (const float4*)(Z   + (size_t)d1 * HID);

    float4 a0 = Ya0[sub];       float4 b0 = Zb0[sub];
    float4 a1 = Ya0[sub + 8];   float4 b1 = Zb0[sub + 8];
    float4 a2 = Ya0[sub + 16];  float4 b2 = Zb0[sub + 16];
    float4 a3 = Ya0[sub + 24];  float4 b3 = Zb0[sub + 24];
    float4 c0 = Ya1[sub];       float4 e0v = Zb1[sub];
    float4 c1 = Ya1[sub + 8];   float4 e1v = Zb1[sub + 8];
    float4 c2 = Ya1[sub + 16];  float4 e2v = Zb1[sub + 16];
    float4 c3 = Ya1[sub + 24];  float4 e3v = Zb1[sub + 24];

    float v0 = a0.x * b0.x + a0.y * b0.y + a0.z * b0.z + a0.w * b0.w;
    v0 += a1.x * b1.x + a1.y * b1.y + a1.z * b1.z + a1.w * b1.w;
    v0 += a2.x * b2.x + a2.y * b2.y + a2.z * b2.z + a2.w * b2.w;
    v0 += a3.x * b3.x + a3.y * b3.y + a3.z * b3.z + a3.w * b3.w;

    float v1 = c0.x * e0v.x + c0.y * e0v.y + c0.z * e0v.z + c0.w * e0v.w;
    v1 += c1.x * e1v.x + c1.y * e1v.y + c1.z * e1v.z + c1.w * e1v.w;
    v1 += c2.x * e2v.x + c2.y * e2v.y + c2.z * e2v.z + c2.w * e2v.w;
    v1 += c3.x * e3v.x + c3.y * e3v.y + c3.z * e3v.z + c3.w * e3v.w;

    v0 += __shfl_xor_sync(FULL, v0, 1);
    v1 += __shfl_xor_sync(FULL, v1, 1);
    v0 += __shfl_xor_sync(FULL, v0, 2);
    v1 += __shfl_xor_sync(FULL, v1, 2);
    v0 += __shfl_xor_sync(FULL, v0, 4);
    v1 += __shfl_xor_sync(FULL, v1, 4);

    float vg0 = __shfl_sync(FULL, v0, (lane & 3) << 3);
    float vg1 = __shfl_sync(FULL, v1, (lane & 3) << 3);
    float vg  = (lane < 4) ? vg0 : vg1;

    if (lane < 8) {
        long long e = e0 + lane;
        if (e < E) out[e] = 1.0f / (1.0f + expf(-vg));
    }
}

// ---------------------------------------------------------------------------
extern "C" void kernel_launch(void* const* d_in, const int* in_sizes, int n_in,
                              void* d_out, int out_size) {
    // Map inputs by element count: W = 16384; z = largest; edge_index = the rest.
    int wi = -1;
    for (int i = 0; i < n_in; i++) if (in_sizes[i] == HID * HID) { wi = i; break; }
    int zi = -1;
    for (int i = 0; i < n_in; i++) {
        if (i == wi) continue;
        if (zi < 0 || in_sizes[i] > in_sizes[zi]) zi = i;
    }
    int eii = -1;
    for (int i = 0; i < n_in; i++) if (i != wi && i != zi) { eii = i; break; }

    const float* W  = (const float*)d_in[wi];
    const float* z  = (const float*)d_in[zi];
    const void*  ei = d_in[eii];

    float* out = (float*)d_out;
    int nrows = in_sizes[zi] / HID;
    int E     = in_sizes[eii] / 2;

    symm_kernel<<<64, 256>>>(W, (const int*)ei);

    int smem = 2 * 128 * PAD_W * (int)sizeof(uint32_t);   // 69632 B
    cudaFuncSetAttribute(gemm_mma_kernel, cudaFuncAttributeMaxDynamicSharedMemorySize, smem);
    int gblocks = (nrows + 127) / 128;
    gemm_mma_kernel<<<gblocks, 256, smem>>>(z, nrows);

    int eblocks = (E + 63) / 64;
    edge_kernel<<<eblocks, 256>>>(ei, z, out, E);
}

// round 13
// speedup vs baseline: 1.9576x; 1.0122x over previous
#include <cuda_runtime.h>
#include <cuda_bf16.h>
#include <math.h>
#include <stdint.h>

// ---------------------------------------------------------------------------
// DistMultDecoder: out[e] = sigmoid( z[src_e] . (W + W^T) . z[dst_e] )
//   Wsym = W + W^T ; Y = Z @ Wsym ; out[e] = sigmoid(dot(Y[src], Z[dst]))
// GEMM: mma.sync bf16 2-term Dekker split  Y = Zh*Wh + Zh*Wl + Zl*Wh.
// A path software-pipelined: k-step A loads double-buffered in registers.
// Edge: flat, 8 lanes/edge, 8 edges/warp, 16 LDG.128 in flight.
// ---------------------------------------------------------------------------

#define HID 128
#define MAX_NODES 100000
#define PAD_W 68   // words/row: frag LDS bank = (4g+t) mod 32, conflict-free

__device__ float g_Y[(size_t)MAX_NODES * HID];
__device__ int   g_is64;
__device__ __nv_bfloat16 g_Wh[HID * HID];   // Wsym hi, row-major [n][k]
__device__ __nv_bfloat16 g_Wl[HID * HID];   // Wsym lo

// ------- kernel 1: Wsym = W + W^T -> bf16 hi/lo ; + index-dtype detect ------
__global__ void symm_kernel(const float* __restrict__ W, const int* __restrict__ ei32) {
    if (blockIdx.x == 0 && threadIdx.x == 0) {
        int s = 0;
        #pragma unroll
        for (int i = 1; i < 64; i += 2) s |= ei32[i];
        g_is64 = (s == 0) ? 1 : 0;          // int64 LE small values: odd words all 0
    }
    int i = blockIdx.x * blockDim.x + threadIdx.x;   // 0..16383
    int n = i >> 7, k = i & 127;
    float v = W[n * HID + k] + W[k * HID + n];       // Wsym[n][k]
    __nv_bfloat16 hi = __float2bfloat16(v);
    __nv_bfloat16 lo = __float2bfloat16(v - __bfloat162float(hi));
    g_Wh[i] = hi;
    g_Wl[i] = lo;
}

// ---------------- kernel 2: Y = Z @ Wsym via mma.sync bf16 ------------------
#define MMA16816(D, A0, A1, A2, A3, B0, B1)                                   \
    asm volatile("mma.sync.aligned.m16n8k16.row.col.f32.bf16.bf16.f32 "       \
                 "{%0,%1,%2,%3}, {%4,%5,%6,%7}, {%8,%9}, {%0,%1,%2,%3};"      \
                 : "+f"(D[0]), "+f"(D[1]), "+f"(D[2]), "+f"(D[3])             \
                 : "r"(A0), "r"(A1), "r"(A2), "r"(A3), "r"(B0), "r"(B1))

__device__ __forceinline__ uint32_t bf2_hi(float2 p) {
    __nv_bfloat162 h = __floats2bfloat162_rn(p.x, p.y);
    return *(uint32_t*)&h;
}
__device__ __forceinline__ uint32_t bf2_lo(float2 p, uint32_t hbits) {
    __nv_bfloat162 h = *(__nv_bfloat162*)&hbits;
    __nv_bfloat162 l = __floats2bfloat162_rn(p.x - __bfloat162float(h.x),
                                             p.y - __bfloat162float(h.y));
    return *(uint32_t*)&l;
}

__global__ __launch_bounds__(256) void gemm_mma_kernel(const float* __restrict__ Z, int nrows) {
    extern __shared__ __align__(16) uint32_t sh[];
    uint32_t* WH = sh;                    // 128 x 68 words (bf16x2)
    uint32_t* WL = sh + 128 * PAD_W;

    int tid = threadIdx.x;

    // ---- stage W hi/lo into padded smem (8192 words each, coalesced) ----
    {
        const uint32_t* gwh = (const uint32_t*)g_Wh;
        const uint32_t* gwl = (const uint32_t*)g_Wl;
        #pragma unroll
        for (int i = 0; i < 32; i++) {
            int idx  = tid + 256 * i;        // 0..8191
            int row  = idx >> 6;
            int word = idx & 63;
            WH[row * PAD_W + word] = gwh[idx];
            WL[row * PAD_W + word] = gwl[idx];
        }
    }
    __syncthreads();

    int lane = tid & 31, w = tid >> 5;
    int g = lane >> 2, t = lane & 3;
    int r0 = (w & 3) * 32;        // warp row base within CTA tile
    int n0 = (w >> 2) * 64;       // warp col base

    // Per-thread A row pointers (clamped for OOB; garbage accums never stored)
    int base = blockIdx.x * 128 + r0 + g;
    const float* zp[4];
    #pragma unroll
    for (int q = 0; q < 4; q++) {
        int r = base + 8 * q;
        if (r >= nrows) r = nrows - 1;
        zp[q] = Z + (size_t)r * HID + 2 * t;
    }

    // Two n-halves of 4 n-tiles each: 32 accumulators live at a time.
    #pragma unroll
    for (int nh = 0; nh < 2; nh++) {
        int nbase = n0 + nh * 32;

        float d[2][4][4];
        #pragma unroll
        for (int m = 0; m < 2; m++)
            #pragma unroll
            for (int n = 0; n < 4; n++)
                #pragma unroll
                for (int q = 0; q < 4; q++) d[m][n][q] = 0.f;

        // ---- prefetch k-step 0 ----   j = q*2 + h : addr = zp[q] + 16*ks + 8h
        float2 pn[8];
        #pragma unroll
        for (int j = 0; j < 8; j++)
            pn[j] = *(const float2*)(zp[j >> 1] + 8 * (j & 1));

        #pragma unroll
        for (int ks = 0; ks < 8; ks++) {
            float2 p[8];
            #pragma unroll
            for (int j = 0; j < 8; j++) p[j] = pn[j];

            // ---- prefetch next k-step while current computes ----
            if (ks < 7) {
                int kb2 = (ks + 1) * 16;
                #pragma unroll
                for (int j = 0; j < 8; j++)
                    pn[j] = *(const float2*)(zp[j >> 1] + kb2 + 8 * (j & 1));
            }

            // ---- convert current step to bf16 hi/lo ----
            uint32_t ah[2][4], al[2][4];
            #pragma unroll
            for (int m = 0; m < 2; m++) {
                ah[m][0] = bf2_hi(p[4 * m + 0]);     // row g(+16m),  k lo
                ah[m][1] = bf2_hi(p[4 * m + 2]);     // row g+8(+16m), k lo
                ah[m][2] = bf2_hi(p[4 * m + 1]);     // row g(+16m),  k hi
                ah[m][3] = bf2_hi(p[4 * m + 3]);     // row g+8(+16m), k hi
                al[m][0] = bf2_lo(p[4 * m + 0], ah[m][0]);
                al[m][1] = bf2_lo(p[4 * m + 2], ah[m][1]);
                al[m][2] = bf2_lo(p[4 * m + 1], ah[m][2]);
                al[m][3] = bf2_lo(p[4 * m + 3], ah[m][3]);
            }

            int kw = ks * 8 + t;
            #pragma unroll
            for (int n = 0; n < 4; n++) {
                int nb = (nbase + 8 * n + g) * PAD_W + kw;
                uint32_t bh0 = WH[nb], bh1 = WH[nb + 4];
                uint32_t bl0 = WL[nb], bl1 = WL[nb + 4];
                #pragma unroll
                for (int m = 0; m < 2; m++) {
                    MMA16816(d[m][n], ah[m][0], ah[m][1], ah[m][2], ah[m][3], bh0, bh1);
                    MMA16816(d[m][n], ah[m][0], ah[m][1], ah[m][2], ah[m][3], bl0, bl1);
                    MMA16816(d[m][n], al[m][0], al[m][1], al[m][2], al[m][3], bh0, bh1);
                }
            }
        }

        // ---- epilogue for this n-half ----
        #pragma unroll
        for (int m = 0; m < 2; m++) {
            int r = base + 16 * m;
            #pragma unroll
            for (int n = 0; n < 4; n++) {
                int c = nbase + 8 * n + 2 * t;
                if (r < nrows)
                    *(float2*)(g_Y + (size_t)r * HID + c) = make_float2(d[m][n][0], d[m][n][1]);
                if (r + 8 < nrows)
                    *(float2*)(g_Y + (size_t)(r + 8) * HID + c) = make_float2(d[m][n][2], d[m][n][3]);
            }
        }
    }
}

// ------------------- kernel 3: per-edge gather + dot + sigmoid --------------
// 8 lanes/edge, 8 edges/warp in two 4-edge batches; 16 LDG.128 in flight.
__global__ __launch_bounds__(256) void edge_kernel(const void* __restrict__ ei,
                                                   const float* __restrict__ Z,
                                                   float* __restrict__ out, int E) {
    const unsigned FULL = 0xFFFFFFFFu;
    int gtid  = blockIdx.x * blockDim.x + threadIdx.x;
    int warp  = gtid >> 5;
    int lane  = gtid & 31;
    int grp   = lane >> 3;       // 0..3
    int sub   = lane & 7;        // 0..7

    long long e0 = (long long)warp * 8;
    if (e0 >= E) return;

    long long myidx = 0;
    int is64 = g_is64;
    if (lane < 16) {
        long long e = e0 + (lane & 7);
        if (e >= E) e = 0;
        size_t off = (lane < 8) ? (size_t)e : (size_t)E + (size_t)e;
        if (is64) myidx = ((const long long*)ei)[off];
        else      myidx = ((const int*)ei)[off];
    }
    long long s0 = __shfl_sync(FULL, myidx, grp);
    long long s1 = __shfl_sync(FULL, myidx, 4 + grp);
    long long d0 = __shfl_sync(FULL, myidx, 8 + grp);
    long long d1 = __shfl_sync(FULL, myidx, 12 + grp);

    const float4* Ya0 = (const float4*)(g_Y + (size_t)s0 * HID);
    const float4* Zb0 = (const float4*)(Z   + (size_t)d0 * HID);
    const float4* Ya1 = (const float4*)(g_Y + (size_t)s1 * HID);
    const float4* Zb1 = (const float4*)(Z   + (size_t)d1 * HID);

    float4 a0 = Ya0[sub];       float4 b0 = Zb0[sub];
    float4 a1 = Ya0[sub + 8];   float4 b1 = Zb0[sub + 8];
    float4 a2 = Ya0[sub + 16];  float4 b2 = Zb0[sub + 16];
    float4 a3 = Ya0[sub + 24];  float4 b3 = Zb0[sub + 24];
    float4 c0 = Ya1[sub];       float4 e0v = Zb1[sub];
    float4 c1 = Ya1[sub + 8];   float4 e1v = Zb1[sub + 8];
    float4 c2 = Ya1[sub + 16];  float4 e2v = Zb1[sub + 16];
    float4 c3 = Ya1[sub + 24];  float4 e3v = Zb1[sub + 24];

    float v0 = a0.x * b0.x + a0.y * b0.y + a0.z * b0.z + a0.w * b0.w;
    v0 += a1.x * b1.x + a1.y * b1.y + a1.z * b1.z + a1.w * b1.w;
    v0 += a2.x * b2.x + a2.y * b2.y + a2.z * b2.z + a2.w * b2.w;
    v0 += a3.x * b3.x + a3.y * b3.y + a3.z * b3.z + a3.w * b3.w;

    float v1 = c0.x * e0v.x + c0.y * e0v.y + c0.z * e0v.z + c0.w * e0v.w;
    v1 += c1.x * e1v.x + c1.y * e1v.y + c1.z * e1v.z + c1.w * e1v.w;
    v1 += c2.x * e2v.x + c2.y * e2v.y + c2.z * e2v.z + c2.w * e2v.w;
    v1 += c3.x * e3v.x + c3.y * e3v.y + c3.z * e3v.z + c3.w * e3v.w;

    v0 += __shfl_xor_sync(FULL, v0, 1);
    v1 += __shfl_xor_sync(FULL, v1, 1);
    v0 += __shfl_xor_sync(FULL, v0, 2);
    v1 += __shfl_xor_sync(FULL, v1, 2);
    v0 += __shfl_xor_sync(FULL, v0, 4);
    v1 += __shfl_xor_sync(FULL, v1, 4);

    float vg0 = __shfl_sync(FULL, v0, (lane & 3) << 3);
    float vg1 = __shfl_sync(FULL, v1, (lane & 3) << 3);
    float vg  = (lane < 4) ? vg0 : vg1;

    if (lane < 8) {
        long long e = e0 + lane;
        if (e < E) out[e] = 1.0f / (1.0f + expf(-vg));
    }
}

// ---------------------------------------------------------------------------
extern "C" void kernel_launch(void* const* d_in, const int* in_sizes, int n_in,
                              void* d_out, int out_size) {
    // Map inputs by element count: W = 16384; z = largest; edge_index = the rest.
    int wi = -1;
    for (int i = 0; i < n_in; i++) if (in_sizes[i] == HID * HID) { wi = i; break; }
    int zi = -1;
    for (int i = 0; i < n_in; i++) {
        if (i == wi) continue;
        if (zi < 0 || in_sizes[i] > in_sizes[zi]) zi = i;
    }
    int eii = -1;
    for (int i = 0; i < n_in; i++) if (i != wi && i != zi) { eii = i; break; }

    const float* W  = (const float*)d_in[wi];
    const float* z  = (const float*)d_in[zi];
    const void*  ei = d_in[eii];

    float* out = (float*)d_out;
    int nrows = in_sizes[zi] / HID;
    int E     = in_sizes[eii] / 2;

    symm_kernel<<<64, 256>>>(W, (const int*)ei);

    int smem = 2 * 128 * PAD_W * (int)sizeof(uint32_t);   // 69632 B
    cudaFuncSetAttribute(gemm_mma_kernel, cudaFuncAttributeMaxDynamicSharedMemorySize, smem);
    int gblocks = (nrows + 127) / 128;
    gemm_mma_kernel<<<gblocks, 256, smem>>>(z, nrows);

    int eblocks = (E + 63) / 64;
    edge_kernel<<<eblocks, 256>>>(ei, z, out, E);
}